// round 1
// baseline (speedup 1.0000x reference)
#include <cuda_runtime.h>
#include <cuda_bf16.h>
#include <cstdint>

// Embedding gather: out[b,s,:] = embedding[input_ids[b,s],:]
// input_ids: [2,2048] int32 -> 4096 tokens
// embedding: [32000,1024] fp32
// out:       [4096,1024] fp32
//
// One CTA per token row. 256 threads x float4 = 1024 floats = one row.
// Fully coalesced 16B accesses on both load and store.

#define FEATURES 1024
#define VEC4 (FEATURES / 4)   // 256 float4 per row

__global__ __launch_bounds__(256, 8)
void wordembed_gather_kernel(const int* __restrict__ input_ids,
                             const float4* __restrict__ embedding,
                             float4* __restrict__ out,
                             int n_tokens) {
    int row = blockIdx.x;
    if (row >= n_tokens) return;

    // Uniform per-block index load (broadcast via L1/const path)
    int id = __ldg(&input_ids[row]);

    const float4* src = embedding + (size_t)id * VEC4;
    float4* dst       = out       + (size_t)row * VEC4;

    int t = threadIdx.x;           // 0..255, exactly VEC4 threads
    dst[t] = __ldg(&src[t]);
}

extern "C" void kernel_launch(void* const* d_in, const int* in_sizes, int n_in,
                              void* d_out, int out_size) {
    const int*    input_ids = (const int*)d_in[0];
    const float4* embedding = (const float4*)d_in[1];
    float4*       out       = (float4*)d_out;

    int n_tokens = in_sizes[0];    // 2*2048 = 4096

    wordembed_gather_kernel<<<n_tokens, 256>>>(input_ids, embedding, out, n_tokens);
}